// round 16
// baseline (speedup 1.0000x reference)
#include <cuda_runtime.h>
#include <cuda_bf16.h>
#include <cstdint>
#include <cstring>
#include <cmath>
#include <algorithm>
#include <thread>
#include <vector>

#define TF_PARTITIONABLE 1

#define S_TOK   4608
#define HW_TOK  4096
#define NCH     256
#define HALF_BAND 230
#define NRAND   115
#define RAND_PITCH 116
#define BWIN_W  18

// ---------------- device scratch ----------------
__device__ float    g_feats[S_TOK * NCH];
__device__ float    g_part[32 * 256 * 256];
__device__ float    g_qkv[S_TOK * 768];
__device__ float    g_ctx[HW_TOK * NCH];
__device__ float    g_lo[HW_TOK * NCH];
__device__ float    g_lnlo[HW_TOK * NCH];
__device__ float    g_h1[HW_TOK * 1024];
__device__ float    g_lo2[HW_TOK * NCH];
__device__ uint32_t g_bandmask[HW_TOK * BWIN_W];
__device__ float    g_m[HW_TOK * 8];
__device__ float    g_l[HW_TOK * 8];
__device__ unsigned short g_rand16[HW_TOK * RAND_PITCH];
__device__ int      g_cnt[HW_TOK];
// rand-pass partials + bf16 K/V
__device__ float    g_mr[HW_TOK * 8];
__device__ float    g_lr[HW_TOK * 8];
__device__ float    g_or[HW_TOK * NCH];
__device__ __nv_bfloat16 g_kvbf[S_TOK * 512];   // [tok][0:256)=K, [256:512)=V
// pre-rounded tf32 weight copies
__device__ float    g_wq[768 * 256];
__device__ float    g_wo[256 * 256];
__device__ float    g_w1[1024 * 256];
__device__ float    g_w2[256 * 1024];

// ---------------- tf32 helpers ----------------
__device__ __forceinline__ uint32_t f2tf(float f)
{ uint32_t u; asm("cvt.rna.tf32.f32 %0, %1;" : "=r"(u) : "f"(f)); return u; }

__device__ __forceinline__ float f2tff(float f)
{ return __uint_as_float(f2tf(f)); }

__device__ __forceinline__ void mma_tf32(float* c, const uint32_t* a, const uint32_t* b)
{
    asm volatile(
        "mma.sync.aligned.m16n8k8.row.col.f32.tf32.tf32.f32 "
        "{%0,%1,%2,%3},{%4,%5,%6,%7},{%8,%9},{%0,%1,%2,%3};"
        : "+f"(c[0]), "+f"(c[1]), "+f"(c[2]), "+f"(c[3])
        : "r"(a[0]), "r"(a[1]), "r"(a[2]), "r"(a[3]), "r"(b[0]), "r"(b[1]));
}

__device__ __forceinline__ float gelu_f(float v)
{ return 0.5f * v * (1.0f + erff(v * 0.70710678118654752f)); }

// ---------------- weight pre-rounding ----------------
__global__ __launch_bounds__(256) void cvt_tf32_k(const float* __restrict__ src,
                                                  float* __restrict__ dst, int n4)
{
    int i = blockIdx.x * 256 + threadIdx.x;
    if (i < n4) {
        float4 v = ((const float4*)src)[i];
        v.x = f2tff(v.x); v.y = f2tff(v.y); v.z = f2tff(v.z); v.w = f2tff(v.w);
        ((float4*)dst)[i] = v;
    }
}

// ---------------- K/V -> bf16 for the rand pass ----------------
__global__ __launch_bounds__(256) void conv_kv_k(const float* __restrict__ qkv)
{
    int t = blockIdx.x, c = threadIdx.x;
    g_kvbf[(size_t)t * 512 + c]       = __float2bfloat16(qkv[(size_t)t * 768 + 256 + c]);
    g_kvbf[(size_t)t * 512 + 256 + c] = __float2bfloat16(qkv[(size_t)t * 768 + 512 + c]);
}

// ---------------- LN of local tokens (emits tf32-rounded feats) ----------------
__global__ __launch_bounds__(256) void ln_local_k(
    const float* __restrict__ x, const float* __restrict__ pos,
    const float* __restrict__ g, const float* __restrict__ b)
{
    __shared__ float tile[256][33];
    const int t0 = blockIdx.x * 32;
    const int lane = threadIdx.x & 31, wid = threadIdx.x >> 5;
    #pragma unroll 8
    for (int it = 0; it < 32; it++) {
        int c = it * 8 + wid;
        tile[c][lane] = x[(size_t)c * HW_TOK + t0 + lane];
    }
    __syncthreads();
    for (int tt = 0; tt < 4; tt++) {
        int tok = wid * 4 + tt;
        float v[8], s = 0.f, sq = 0.f;
        #pragma unroll
        for (int i = 0; i < 8; i++) {
            int c = lane + 32 * i;
            v[i] = tile[c][tok] + pos[c];
            s += v[i]; sq += v[i] * v[i];
        }
        #pragma unroll
        for (int o = 16; o; o >>= 1) {
            s  += __shfl_xor_sync(0xffffffffu, s, o);
            sq += __shfl_xor_sync(0xffffffffu, sq, o);
        }
        float m = s * (1.f / 256.f);
        float var = sq * (1.f / 256.f) - m * m;
        float rs = rsqrtf(var + 1e-5f);
        #pragma unroll
        for (int i = 0; i < 8; i++) {
            int c = lane + 32 * i;
            g_feats[(size_t)(t0 + tok) * NCH + c] = f2tff((v[i] - m) * rs * g[c] + b[c]);
        }
    }
}

// ---------------- row LN (emits tf32-rounded) ----------------
__global__ __launch_bounds__(256) void ln_rows_k(
    const float* __restrict__ in,
    const float* __restrict__ g, const float* __restrict__ b,
    float* __restrict__ out)
{
    int row = blockIdx.x, c = threadIdx.x;
    float v = in[(size_t)row * 256 + c];
    float s = v, sq = v * v;
    #pragma unroll
    for (int o = 16; o; o >>= 1) {
        s  += __shfl_xor_sync(0xffffffffu, s, o);
        sq += __shfl_xor_sync(0xffffffffu, sq, o);
    }
    __shared__ float ss[8], qq[8];
    int wid = c >> 5, lane = c & 31;
    if (!lane) { ss[wid] = s; qq[wid] = sq; }
    __syncthreads();
    float ts = 0.f, tq = 0.f;
    #pragma unroll
    for (int i = 0; i < 8; i++) { ts += ss[i]; tq += qq[i]; }
    float m = ts * (1.f / 256.f);
    float var = tq * (1.f / 256.f) - m * m;
    float rs = rsqrtf(var + 1e-5f);
    out[(size_t)row * 256 + c] = f2tff((v - m) * rs * g[c] + b[c]);
}

// ---------------- fused split-K reduce + add + LN + replicate ----------------
__global__ __launch_bounds__(256) void reduce_ln_k(
    const float* __restrict__ part, int stride, int Z,
    const float* __restrict__ add1, const float* __restrict__ add2,
    const float* __restrict__ g, const float* __restrict__ b,
    float* __restrict__ out, int rep)
{
    int row = blockIdx.x, c = threadIdx.x;
    float v = 0.f;
    for (int z = 0; z < Z; z++) v += part[(size_t)z * stride + row * 256 + c];
    v += add1[c] + add2[c];
    float s = v, sq = v * v;
    #pragma unroll
    for (int o = 16; o; o >>= 1) {
        s  += __shfl_xor_sync(0xffffffffu, s, o);
        sq += __shfl_xor_sync(0xffffffffu, sq, o);
    }
    __shared__ float ss[8], qq[8];
    int wid = c >> 5, lane = c & 31;
    if (!lane) { ss[wid] = s; qq[wid] = sq; }
    __syncthreads();
    float ts = 0.f, tq = 0.f;
    #pragma unroll
    for (int i = 0; i < 8; i++) { ts += ss[i]; tq += qq[i]; }
    float m = ts * (1.f / 256.f);
    float var = tq * (1.f / 256.f) - m * m;
    float rs = rsqrtf(var + 1e-5f);
    float o = f2tff((v - m) * rs * g[c] + b[c]);
    for (int k = 0; k < rep; k++)
        out[(size_t)(row * rep + k) * 256 + c] = o;
}

// ---------------- gather-fused A load for adjacency ----------------
template <int G>
__device__ __forceinline__ float4 loadA_g(const float* __restrict__ A, int row, int col, int K)
{
    if (G == 1) {
        int c = col >> 4, i = (col >> 2) & 3;
        int bh = row >> 4, bw = row & 15;
        return *(const float4*)(A + (size_t)c * HW_TOK + (bh * 4 + i) * 64 + bw * 4);
    }
    int c = col >> 6, i = (col >> 3) & 7, j = col & 7;
    int bh = row >> 3, bw = row & 7;
    return *(const float4*)(A + (size_t)c * HW_TOK + (bh * 8 + i) * 64 + bw * 8 + j);
}

// ---------------- tf32 split-K 64x64x32 GEMM with gather-fused A ----------------
template <int G>
__global__ __launch_bounds__(256) void tsplitk_k(
    const float* __restrict__ A, const float* __restrict__ B,
    float* __restrict__ Cpart, int M, int N, int K, int kPerZ)
{
    constexpr int SA = 36;
    __shared__ uint32_t As[64 * SA];
    __shared__ uint32_t Bs[64 * SA];
    const int tid = threadIdx.x;
    const int lane = tid & 31, wid = tid >> 5;
    const int bm = blockIdx.y * 64, bn = blockIdx.x * 64;
    const int m0 = (wid & 3) * 16, n0 = (wid >> 2) * 32;
    const int r = lane >> 2, qc = lane & 3;
    const int row = tid >> 2, col8 = (tid & 3) * 8;
    const int k0 = blockIdx.z * kPerZ;

    float acc[4][4] = {};
    for (int kt = 0; kt < kPerZ; kt += 32) {
        float4 a0 = loadA_g<G>(A, bm + row, k0 + kt + col8, K);
        float4 a1 = loadA_g<G>(A, bm + row, k0 + kt + col8 + 4, K);
        float4 b0 = *(const float4*)(B + (size_t)(bn + row) * K + k0 + kt + col8);
        float4 b1 = *(const float4*)(B + (size_t)(bn + row) * K + k0 + kt + col8 + 4);
        __syncthreads();
        uint32_t* da = &As[row * SA + col8];
        da[0] = f2tf(a0.x); da[1] = f2tf(a0.y); da[2] = f2tf(a0.z); da[3] = f2tf(a0.w);
        da[4] = f2tf(a1.x); da[5] = f2tf(a1.y); da[6] = f2tf(a1.z); da[7] = f2tf(a1.w);
        uint32_t* db = &Bs[row * SA + col8];
        db[0] = f2tf(b0.x); db[1] = f2tf(b0.y); db[2] = f2tf(b0.z); db[3] = f2tf(b0.w);
        db[4] = f2tf(b1.x); db[5] = f2tf(b1.y); db[6] = f2tf(b1.z); db[7] = f2tf(b1.w);
        __syncthreads();
        #pragma unroll
        for (int ks = 0; ks < 4; ks++) {
            int kk = ks * 8;
            uint32_t af[4];
            af[0] = As[(m0 + r) * SA + kk + qc];
            af[1] = As[(m0 + r + 8) * SA + kk + qc];
            af[2] = As[(m0 + r) * SA + kk + qc + 4];
            af[3] = As[(m0 + r + 8) * SA + kk + qc + 4];
            #pragma unroll
            for (int ni = 0; ni < 4; ni++) {
                uint32_t bf[2];
                bf[0] = Bs[(n0 + ni * 8 + r) * SA + kk + qc];
                bf[1] = Bs[(n0 + ni * 8 + r) * SA + kk + qc + 4];
                mma_tf32(acc[ni], af, bf);
            }
        }
    }
    float* Cz = Cpart + (size_t)blockIdx.z * M * N;
    #pragma unroll
    for (int ni = 0; ni < 4; ni++) {
        int c = bn + n0 + ni * 8 + qc * 2;
        Cz[(size_t)(bm + m0 + r) * N + c]         = acc[ni][0];
        Cz[(size_t)(bm + m0 + r) * N + c + 1]     = acc[ni][1];
        Cz[(size_t)(bm + m0 + r + 8) * N + c]     = acc[ni][2];
        Cz[(size_t)(bm + m0 + r + 8) * N + c + 1] = acc[ni][3];
    }
}

// ---------------- tf32 tensor-core GEMM (A and B pre-rounded: no CVT) ----------------
template <int BN, int EPI, bool RND>
__global__ __launch_bounds__(256) void tgemm_k(
    const float* __restrict__ A, const float* __restrict__ B,
    const float* __restrict__ bias, const float* __restrict__ res,
    float* __restrict__ C, int M, int N, int K)
{
    constexpr int SA = 20;
    constexpr int NF = BN / 16;
    __shared__ uint32_t As[2][128 * SA];
    __shared__ uint32_t Bs[2][BN * SA];

    const int tid = threadIdx.x;
    const int lane = tid & 31, wid = tid >> 5;
    const int bm = blockIdx.y * 128, bn = blockIdx.x * BN;
    const int m0 = (wid & 3) * 32;
    const int n0 = (wid >> 2) * (BN / 2);
    const int r = lane >> 2, qc = lane & 3;

    float acc[2][NF][4] = {};

    const int ar = tid >> 1, ac = (tid & 1) * 8;
    const int br = (BN == 128) ? (tid >> 1) : (tid >> 2);
    const int bc = (BN == 128) ? ((tid & 1) * 8) : ((tid & 3) * 4);

    const float* Apt = A + (size_t)(bm + ar) * K + ac;
    const float* Bpt = B + (size_t)(bn + br) * K + bc;

    float4 pa0 = *(const float4*)(Apt);
    float4 pa1 = *(const float4*)(Apt + 4);
    float4 pb0 = *(const float4*)(Bpt);
    float4 pb1;
    if constexpr (BN == 128) pb1 = *(const float4*)(Bpt + 4);

    auto store_stage = [&](int s) {
        *(float4*)&As[s][ar * SA + ac]     = pa0;
        *(float4*)&As[s][ar * SA + ac + 4] = pa1;
        *(float4*)&Bs[s][br * SA + bc]     = pb0;
        if constexpr (BN == 128)
            *(float4*)&Bs[s][br * SA + bc + 4] = pb1;
    };
    auto compute = [&](int s) {
        #pragma unroll
        for (int ks = 0; ks < 2; ks++) {
            int k0 = ks * 8;
            uint32_t af[2][4];
            #pragma unroll
            for (int mi = 0; mi < 2; mi++) {
                int mb = m0 + mi * 16;
                af[mi][0] = As[s][(mb + r) * SA + k0 + qc];
                af[mi][1] = As[s][(mb + r + 8) * SA + k0 + qc];
                af[mi][2] = As[s][(mb + r) * SA + k0 + qc + 4];
                af[mi][3] = As[s][(mb + r + 8) * SA + k0 + qc + 4];
            }
            #pragma unroll
            for (int ni = 0; ni < NF; ni++) {
                uint32_t bf[2];
                bf[0] = Bs[s][(n0 + ni * 8 + r) * SA + k0 + qc];
                bf[1] = Bs[s][(n0 + ni * 8 + r) * SA + k0 + qc + 4];
                mma_tf32(acc[0][ni], af[0], bf);
                mma_tf32(acc[1][ni], af[1], bf);
            }
        }
    };

    store_stage(0);
    __syncthreads();
    int cur = 0;
    const int nst = K / 16;
    for (int st = 1; st < nst; st++) {
        pa0 = *(const float4*)(Apt + st * 16);
        pa1 = *(const float4*)(Apt + st * 16 + 4);
        pb0 = *(const float4*)(Bpt + st * 16);
        if constexpr (BN == 128) pb1 = *(const float4*)(Bpt + st * 16 + 4);
        compute(cur);
        store_stage(cur ^ 1);
        __syncthreads();
        cur ^= 1;
    }
    compute(cur);

    #pragma unroll
    for (int mi = 0; mi < 2; mi++) {
        int rw = bm + m0 + mi * 16 + r;
        int rw2 = rw + 8;
        #pragma unroll
        for (int ni = 0; ni < NF; ni++) {
            int col = bn + n0 + ni * 8 + qc * 2;
            float v0 = acc[mi][ni][0] + bias[col];
            float v1 = acc[mi][ni][1] + bias[col + 1];
            float v2 = acc[mi][ni][2] + bias[col];
            float v3 = acc[mi][ni][3] + bias[col + 1];
            if (EPI == 2) { v0 = gelu_f(v0); v1 = gelu_f(v1); v2 = gelu_f(v2); v3 = gelu_f(v3); }
            if (EPI == 3) {
                v0 += res[(size_t)rw * N + col];  v1 += res[(size_t)rw * N + col + 1];
                v2 += res[(size_t)rw2 * N + col]; v3 += res[(size_t)rw2 * N + col + 1];
            }
            if (RND) { v0 = f2tff(v0); v1 = f2tff(v1); v2 = f2tff(v2); v3 = f2tff(v3); }
            C[(size_t)rw * N + col] = v0;  C[(size_t)rw * N + col + 1] = v1;
            C[(size_t)rw2 * N + col] = v2; C[(size_t)rw2 * N + col + 1] = v3;
        }
    }
}

// ---------------- band flash attention, tf32 mma ----------------
__global__ __launch_bounds__(256) void attn_band_k(const float* __restrict__ qkv,
                                                   float* __restrict__ ctx)
{
    __shared__ uint32_t Qs[64 * 36];
    __shared__ uint32_t Ks[64 * 36];
    __shared__ uint32_t Vt[32 * 68];
    __shared__ float    Ss[64 * 68];
    __shared__ uint32_t mw[64][2];
    __shared__ float    s_m[64], s_l[64], s_al[64];

    const int tid = threadIdx.x;
    const int lane = tid & 31, wid = tid >> 5;
    const int h = blockIdx.y, t0 = blockIdx.x * 64;
    const int r = lane >> 2, qc = lane & 3;
    const float scale = 0.17677669529663687f;
    uint32_t* PsU = (uint32_t*)Ss;

    {
        int tok = tid >> 2, d0 = (tid & 3) * 8;
        float4 q0 = *(const float4*)&qkv[(size_t)(t0 + tok) * 768 + h * 32 + d0];
        float4 q1 = *(const float4*)&qkv[(size_t)(t0 + tok) * 768 + h * 32 + d0 + 4];
        uint32_t* dq = &Qs[tok * 36 + d0];
        dq[0] = __float_as_uint(q0.x); dq[1] = __float_as_uint(q0.y);
        dq[2] = __float_as_uint(q0.z); dq[3] = __float_as_uint(q0.w);
        dq[4] = __float_as_uint(q1.x); dq[5] = __float_as_uint(q1.y);
        dq[6] = __float_as_uint(q1.z); dq[7] = __float_as_uint(q1.w);
    }
    if (tid < 64) { s_m[tid] = -INFINITY; s_l[tid] = 0.f; }

    float o_[4][4] = {};

    int lo_t = (t0 >= HALF_BAND) ? ((t0 - HALF_BAND) >> 6) : 0;
    int hi_t = (t0 + 63 + HALF_BAND) >> 6; if (hi_t > 71) hi_t = 71;

    for (int kt = lo_t; kt <= hi_t; kt++) {
        __syncthreads();
        int kb = kt * 64;
        {
            int tok = tid >> 2, d0 = (tid & 3) * 8;
            float4 k0v = *(const float4*)&qkv[(size_t)(kb + tok) * 768 + 256 + h * 32 + d0];
            float4 k1v = *(const float4*)&qkv[(size_t)(kb + tok) * 768 + 256 + h * 32 + d0 + 4];
            uint32_t* dk = &Ks[tok * 36 + d0];
            dk[0] = __float_as_uint(k0v.x); dk[1] = __float_as_uint(k0v.y);
            dk[2] = __float_as_uint(k0v.z); dk[3] = __float_as_uint(k0v.w);
            dk[4] = __float_as_uint(k1v.x); dk[5] = __float_as_uint(k1v.y);
            dk[6] = __float_as_uint(k1v.z); dk[7] = __float_as_uint(k1v.w);
            float4 v0v = *(const float4*)&qkv[(size_t)(kb + tok) * 768 + 512 + h * 32 + d0];
            float4 v1v = *(const float4*)&qkv[(size_t)(kb + tok) * 768 + 512 + h * 32 + d0 + 4];
            Vt[(d0 + 0) * 68 + tok] = __float_as_uint(v0v.x);
            Vt[(d0 + 1) * 68 + tok] = __float_as_uint(v0v.y);
            Vt[(d0 + 2) * 68 + tok] = __float_as_uint(v0v.z);
            Vt[(d0 + 3) * 68 + tok] = __float_as_uint(v0v.w);
            Vt[(d0 + 4) * 68 + tok] = __float_as_uint(v1v.x);
            Vt[(d0 + 5) * 68 + tok] = __float_as_uint(v1v.y);
            Vt[(d0 + 6) * 68 + tok] = __float_as_uint(v1v.z);
            Vt[(d0 + 7) * 68 + tok] = __float_as_uint(v1v.w);
        }
        if (tid < 128)
            mw[tid >> 1][tid & 1] =
                g_bandmask[(size_t)(t0 + (tid >> 1)) * BWIN_W + (kt - lo_t) * 2 + (tid & 1)];
        __syncthreads();

        {
            const int m0 = (wid & 3) * 16, nh = (wid >> 2) * 32;
            float sf[4][4] = {};
            #pragma unroll
            for (int ks = 0; ks < 4; ks++) {
                int k0 = ks * 8;
                uint32_t af[4];
                af[0] = Qs[(m0 + r) * 36 + k0 + qc];
                af[1] = Qs[(m0 + r + 8) * 36 + k0 + qc];
                af[2] = Qs[(m0 + r) * 36 + k0 + qc + 4];
                af[3] = Qs[(m0 + r + 8) * 36 + k0 + qc + 4];
                #pragma unroll
                for (int ni = 0; ni < 4; ni++) {
                    uint32_t bf[2];
                    bf[0] = Ks[(nh + ni * 8 + r) * 36 + k0 + qc];
                    bf[1] = Ks[(nh + ni * 8 + r) * 36 + k0 + qc + 4];
                    mma_tf32(sf[ni], af, bf);
                }
            }
            #pragma unroll
            for (int ni = 0; ni < 4; ni++) {
                int c0 = nh + ni * 8 + qc * 2;
                int rowA = m0 + r, rowB = m0 + r + 8;
                uint32_t wA0 = (mw[rowA][c0 >> 5] >> (c0 & 31)) & 1u;
                uint32_t wA1 = (mw[rowA][(c0 + 1) >> 5] >> ((c0 + 1) & 31)) & 1u;
                uint32_t wB0 = (mw[rowB][c0 >> 5] >> (c0 & 31)) & 1u;
                uint32_t wB1 = (mw[rowB][(c0 + 1) >> 5] >> ((c0 + 1) & 31)) & 1u;
                Ss[rowA * 68 + c0]     = wA0 ? sf[ni][0] * scale : -INFINITY;
                Ss[rowA * 68 + c0 + 1] = wA1 ? sf[ni][1] * scale : -INFINITY;
                Ss[rowB * 68 + c0]     = wB0 ? sf[ni][2] * scale : -INFINITY;
                Ss[rowB * 68 + c0 + 1] = wB1 ? sf[ni][3] * scale : -INFINITY;
            }
        }
        __syncthreads();

        {
            int row = tid >> 2, c0 = (tid & 3) * 16;
            float sv[16], mx = -INFINITY;
            #pragma unroll
            for (int j = 0; j < 16; j++) {
                sv[j] = Ss[row * 68 + c0 + j];
                mx = fmaxf(mx, sv[j]);
            }
            mx = fmaxf(mx, __shfl_xor_sync(0xffffffffu, mx, 1));
            mx = fmaxf(mx, __shfl_xor_sync(0xffffffffu, mx, 2));
            float m_old = s_m[row];
            float m_new = fmaxf(m_old, mx);
            float al, ps = 0.f;
            if (m_new == -INFINITY) {
                al = 1.f;
                #pragma unroll
                for (int j = 0; j < 16; j++)
                    PsU[row * 68 + c0 + j] = 0u;
            } else {
                al = __expf(m_old - m_new);
                #pragma unroll
                for (int j = 0; j < 16; j++) {
                    float pv = __expf(sv[j] - m_new);
                    ps += pv;
                    PsU[row * 68 + c0 + j] = f2tf(pv);
                }
            }
            ps += __shfl_xor_sync(0xffffffffu, ps, 1);
            ps += __shfl_xor_sync(0xffffffffu, ps, 2);
            if ((tid & 3) == 0) {
                s_l[row] = s_l[row] * al + ps;
                s_m[row] = m_new;
                s_al[row] = al;
            }
        }
        __syncthreads();

        if (wid < 4) {
            const int m0 = wid * 16;
            float alA = s_al[m0 + r], alB = s_al[m0 + r + 8];
            #pragma unroll
            for (int ni = 0; ni < 4; ni++) {
                o_[ni][0] *= alA; o_[ni][1] *= alA;
                o_[ni][2] *= alB; o_[ni][3] *= alB;
            }
            #pragma unroll
            for (int ks = 0; ks < 8; ks++) {
                int k0 = ks * 8;
                uint32_t af[4];
                af[0] = PsU[(m0 + r) * 68 + k0 + qc];
                af[1] = PsU[(m0 + r + 8) * 68 + k0 + qc];
                af[2] = PsU[(m0 + r) * 68 + k0 + qc + 4];
                af[3] = PsU[(m0 + r + 8) * 68 + k0 + qc + 4];
                #pragma unroll
                for (int ni = 0; ni < 4; ni++) {
                    uint32_t bf[2];
                    bf[0] = Vt[(ni * 8 + r) * 68 + k0 + qc];
                    bf[1] = Vt[(ni * 8 + r) * 68 + k0 + qc + 4];
                    mma_tf32(o_[ni], af, bf);
                }
            }
        }
    }
    __syncthreads();

    if (wid < 4) {
        const int m0 = wid * 16;
        int rowA = t0 + m0 + r, rowB = rowA + 8;
        #pragma unroll
        for (int ni = 0; ni < 4; ni++) {
            int col = h * 32 + ni * 8 + qc * 2;
            ctx[(size_t)rowA * 256 + col]     = o_[ni][0];
            ctx[(size_t)rowA * 256 + col + 1] = o_[ni][1];
            ctx[(size_t)rowB * 256 + col]     = o_[ni][2];
            ctx[(size_t)rowB * 256 + col + 1] = o_[ni][3];
        }
    }
    if (tid < 64) {
        g_m[(t0 + tid) * 8 + h] = s_m[tid];
        g_l[(t0 + tid) * 8 + h] = s_l[tid];
    }
}

// ---------------- independent random-key partial softmax (bf16 K/V) ----------------
__global__ __launch_bounds__(256) void attn_rand_ind_k(const float* __restrict__ qkv)
{
    __shared__ float sS[8][120];
    __shared__ int   sK[NRAND + 1];
    const int row = blockIdx.x;
    const int w = threadIdx.x >> 5;
    const int lane = threadIdx.x & 31;
    const int ch = w * 32 + lane;
    const float scale = 0.17677669529663687f;

    const int cnt = g_cnt[row];
    if (threadIdx.x < cnt)
        sK[threadIdx.x] = g_rand16[(size_t)row * RAND_PITCH + threadIdx.x];
    __syncthreads();

    if (cnt == 0) {
        if (lane == 0) { g_mr[row * 8 + w] = -INFINITY; g_lr[row * 8 + w] = 0.f; }
        g_or[(size_t)row * 256 + ch] = 0.f;
        return;
    }

    float qv = qkv[(size_t)row * 768 + ch];

    for (int i = 0; i < cnt; i++) {
        float kv = __bfloat162float(g_kvbf[(size_t)sK[i] * 512 + ch]);
        float s = qv * kv;
        #pragma unroll
        for (int off = 16; off; off >>= 1)
            s += __shfl_xor_sync(0xffffffffu, s, off);
        if (lane == 0) sS[w][i] = s * scale;
    }
    __syncwarp();

    float mx = -INFINITY;
    for (int i = lane; i < cnt; i += 32) mx = fmaxf(mx, sS[w][i]);
    #pragma unroll
    for (int off = 16; off; off >>= 1)
        mx = fmaxf(mx, __shfl_xor_sync(0xffffffffu, mx, off));
    float psum = 0.f;
    for (int i = lane; i < cnt; i += 32) {
        float p = __expf(sS[w][i] - mx);
        sS[w][i] = p;
        psum += p;
    }
    #pragma unroll
    for (int off = 16; off; off >>= 1)
        psum += __shfl_xor_sync(0xffffffffu, psum, off);
    __syncwarp();

    float o = 0.f;
    for (int i = 0; i < cnt; i++)
        o += sS[w][i] * __bfloat162float(g_kvbf[(size_t)sK[i] * 512 + 256 + ch]);

    if (lane == 0) { g_mr[row * 8 + w] = mx; g_lr[row * 8 + w] = psum; }
    g_or[(size_t)row * 256 + ch] = o;
}

// ---------------- merge band + rand partial softmaxes ----------------
__global__ __launch_bounds__(256) void merge_attn_k(float* __restrict__ ctx)
{
    int row = blockIdx.x, ch = threadIdx.x, w = ch >> 5;
    float m_b = g_m[row * 8 + w], l_b = g_l[row * 8 + w];
    float m_r = g_mr[row * 8 + w], l_r = g_lr[row * 8 + w];
    float m = fmaxf(m_b, m_r);
    float fb = __expf(m_b - m);
    float fr = (m_r == -INFINITY) ? 0.f : __expf(m_r - m);
    float ob = ctx[(size_t)row * 256 + ch];
    float orr = g_or[(size_t)row * 256 + ch];
    float l = l_b * fb + l_r * fr;
    ctx[(size_t)row * 256 + ch] = f2tff((ob * fb + orr * fr) / l);
}

// ---------------- final transpose + residual ----------------
__global__ __launch_bounds__(256) void finalize_k(const float* __restrict__ x,
                                                  float* __restrict__ out)
{
    __shared__ float t[32][33];
    int bhw = blockIdx.x * 32, bc = blockIdx.y * 32;
    int tx = threadIdx.x & 31, ty = threadIdx.x >> 5;
    for (int i = ty; i < 32; i += 8)
        t[i][tx] = g_lo2[(size_t)(bhw + i) * 256 + bc + tx];
    __syncthreads();
    for (int i = ty; i < 32; i += 8) {
        int c = bc + i, hw = bhw + tx;
        out[(size_t)c * HW_TOK + hw] = t[tx][i] + x[(size_t)c * HW_TOK + hw];
    }
}

// ================= host: threefry2x32 + jax mask replication =================
static inline uint32_t rotl32(uint32_t x, int r) { return (x << r) | (x >> (32 - r)); }

static void tf2x32(uint32_t k0, uint32_t k1, uint32_t x0, uint32_t x1,
                   uint32_t& o0, uint32_t& o1)
{
    uint32_t ks0 = k0, ks1 = k1, ks2 = k0 ^ k1 ^ 0x1BD11BDAu;
    static const int ra[4] = {13, 15, 26, 6}, rb[4] = {17, 29, 16, 24};
    x0 += ks0; x1 += ks1;
    for (int i = 0; i < 4; i++) { x0 += x1; x1 = rotl32(x1, ra[i]); x1 ^= x0; }
    x0 += ks1; x1 += ks2 + 1;
    for (int i = 0; i < 4; i++) { x0 += x1; x1 = rotl32(x1, rb[i]); x1 ^= x0; }
    x0 += ks2; x1 += ks0 + 2;
    for (int i = 0; i < 4; i++) { x0 += x1; x1 = rotl32(x1, ra[i]); x1 ^= x0; }
    x0 += ks0; x1 += ks1 + 3;
    for (int i = 0; i < 4; i++) { x0 += x1; x1 = rotl32(x1, rb[i]); x1 ^= x0; }
    x0 += ks1; x1 += ks2 + 4;
    for (int i = 0; i < 4; i++) { x0 += x1; x1 = rotl32(x1, ra[i]); x1 ^= x0; }
    x0 += ks2; x1 += ks0 + 5;
    o0 = x0; o1 = x1;
}

static void split2(uint32_t k0, uint32_t k1,
                   uint32_t& a0, uint32_t& a1, uint32_t& s0, uint32_t& s1)
{
#if TF_PARTITIONABLE
    tf2x32(k0, k1, 0u, 0u, a0, a1);
    tf2x32(k0, k1, 0u, 1u, s0, s1);
#else
    uint32_t w0, w2, w1, w3;
    tf2x32(k0, k1, 0u, 2u, w0, w2);
    tf2x32(k0, k1, 1u, 3u, w1, w3);
    a0 = w0; a1 = w1; s0 = w2; s1 = w3;
#endif
}

static void bits_n(uint32_t k0, uint32_t k1, uint32_t* out)
{
#if TF_PARTITIONABLE
    for (uint32_t i = 0; i < S_TOK; i++) {
        uint32_t o0, o1;
        tf2x32(k0, k1, 0u, i, o0, o1);
        out[i] = o0 ^ o1;
    }
#else
    const uint32_t half = S_TOK / 2;
    for (uint32_t i = 0; i < half; i++) {
        uint32_t o0, o1;
        tf2x32(k0, k1, i, i + half, o0, o1);
        out[i] = o0; out[i + half] = o1;
    }
#endif
}

static void row_key(int r, uint32_t& k0, uint32_t& k1)
{
#if TF_PARTITIONABLE
    tf2x32(0u, 42u, 0u, (uint32_t)r, k0, k1);
#else
    uint32_t j0 = 2u * r, j1 = 2u * r + 1;
    uint32_t o0, o1;
    if (j0 < S_TOK) { tf2x32(0u, 42u, j0, j0 + S_TOK, o0, o1); k0 = o0; }
    else            { tf2x32(0u, 42u, j0 - S_TOK, j0, o0, o1); k0 = o1; }
    if (j1 < S_TOK) { tf2x32(0u, 42u, j1, j1 + S_TOK, o0, o1); k1 = o0; }
    else            { tf2x32(0u, 42u, j1 - S_TOK, j1, o0, o1); k1 = o1; }
#endif
}

static uint32_t       h_bandmask[HW_TOK * BWIN_W];
static unsigned short h_rand16[HW_TOK * RAND_PITCH];
static int            h_cnt[HW_TOK];

static void build_rows(int r0, int r1)
{
    std::vector<uint64_t> buf(S_TOK);
    std::vector<uint32_t> bits(S_TOK);
    std::vector<int> perm(S_TOK);
    for (int r = r0; r < r1; r++) {
        uint32_t k0, k1; row_key(r, k0, k1);
        uint32_t a0, a1, s0, s1;
        split2(k0, k1, a0, a1, s0, s1);
        bits_n(s0, s1, bits.data());
        for (int i = 0; i < S_TOK; i++) buf[i] = ((uint64_t)bits[i] << 32) | (uint32_t)i;
        std::sort(buf.begin(), buf.end());
        for (int i = 0; i < S_TOK; i++) perm[i] = (int)(buf[i] & 0xffffffffu);
        uint32_t b0, b1, t0k, t1k;
        split2(a0, a1, b0, b1, t0k, t1k);
        bits_n(t0k, t1k, bits.data());
        for (int i = 0; i < S_TOK; i++) buf[i] = ((uint64_t)bits[i] << 32) | (uint32_t)i;
        std::sort(buf.begin(), buf.end());

        int t0 = r & ~63;
        int lo_t = (t0 >= HALF_BAND) ? ((t0 - HALF_BAND) >> 6) : 0;
        int hi_t = (t0 + 63 + HALF_BAND) >> 6; if (hi_t > 71) hi_t = 71;
        int base = lo_t * 64, top = hi_t * 64 + 63;

        uint32_t* mrow = h_bandmask + (size_t)r * BWIN_W;
        memset(mrow, 0, BWIN_W * sizeof(uint32_t));
        int lo = r - HALF_BAND; if (lo < 0) lo = 0;
        int hi = r + HALF_BAND; if (hi > S_TOK - 1) hi = S_TOK - 1;
        for (int k = lo; k <= hi; k++) {
            int idx = k - base;
            mrow[idx >> 5] |= 1u << (idx & 31);
        }
        int cnt = 0;
        for (int i = 0; i < NRAND; i++) {
            int k = perm[(int)(buf[i] & 0xffffffffu)];
            if (k >= base && k <= top) {
                int idx = k - base;
                mrow[idx >> 5] |= 1u << (idx & 31);
            } else {
                h_rand16[(size_t)r * RAND_PITCH + cnt++] = (unsigned short)k;
            }
        }
        h_cnt[r] = cnt;
    }
}

// ================= launch =================
extern "C" void kernel_launch(void* const* d_in, const int* in_sizes, int n_in,
                              void* d_out, int out_size)
{
    (void)in_sizes; (void)n_in; (void)out_size;
    const float* x         = (const float*)d_in[0];
    const float* local_pos = (const float*)d_in[1];
    const float* reg_pos0  = (const float*)d_in[2];
    const float* reg_pos1  = (const float*)d_in[3];
    const float* ln_l_g    = (const float*)d_in[4];
    const float* ln_l_b    = (const float*)d_in[5];
    const float* ln_r0_g   = (const float*)d_in[6];
    const float* ln_r0_b   = (const float*)d_in[7];
    const float* ln_r1_g   = (const float*)d_in[8];
    const float* ln_r1_b   = (const float*)d_in[9];
    const float* adj0_w    = (const float*)d_in[10];
    const float* adj0_b    = (const float*)d_in[11];
    const float* adj1_w    = (const float*)d_in[12];
    const float* adj1_b    = (const float*)d_in[13];
    const float* in_w      = (const float*)d_in[14];
    const float* in_b      = (const float*)d_in[15];
    const float* out_w     = (const float*)d_in[16];
    const float* out_b     = (const float*)d_in[17];
    const float* ln_o_g    = (const float*)d_in[18];
    const float* ln_o_b    = (const float*)d_in[19];
    const float* mlp_w1    = (const float*)d_in[20];
    const float* mlp_b1    = (const float*)d_in[21];
    const float* mlp_w2    = (const float*)d_in[22];
    const float* mlp_b2    = (const float*)d_in[23];
    float* out = (float*)d_out;

    {
        unsigned hc = std::thread::hardware_concurrency();
        int nt = (int)(hc ? (hc > 64 ? 64 : hc) : 8);
        std::vector<std::thread> th;
        int per = (HW_TOK + nt - 1) / nt;
        for (int t = 0; t < nt; t++) {
            int r0 = t * per, r1 = r0 + per; if (r1 > HW_TOK) r1 = HW_TOK;
            if (r0 < r1) th.emplace_back(build_rows, r0, r1);
        }
        for (auto& t : th) t.join();
    }

    static cudaStream_t s1 = nullptr, s2 = nullptr, s3 = nullptr;
    static cudaEvent_t e0 = nullptr, e1 = nullptr, e2 = nullptr, e3 = nullptr,
                       e5 = nullptr, eq = nullptr, e4 = nullptr;
    if (!s1) {
        cudaStreamCreateWithFlags(&s1, cudaStreamNonBlocking);
        cudaStreamCreateWithFlags(&s2, cudaStreamNonBlocking);
        cudaStreamCreateWithFlags(&s3, cudaStreamNonBlocking);
        cudaEventCreateWithFlags(&e0, cudaEventDisableTiming);
        cudaEventCreateWithFlags(&e1, cudaEventDisableTiming);
        cudaEventCreateWithFlags(&e2, cudaEventDisableTiming);
        cudaEventCreateWithFlags(&e3, cudaEventDisableTiming);
        cudaEventCreateWithFlags(&e5, cudaEventDisableTiming);
        cudaEventCreateWithFlags(&eq, cudaEventDisableTiming);
        cudaEventCreateWithFlags(&e4, cudaEventDisableTiming);
    }

    void* p;
    cudaGetSymbolAddress(&p, g_feats); float* feats = (float*)p;
    cudaGetSymbolAddress(&p, g_part);  float* part  = (float*)p;
    cudaGetSymbolAddress(&p, g_qkv);   float* qkv   = (float*)p;
    cudaGetSymbolAddress(&p, g_ctx);   float* ctx   = (float*)p;
    cudaGetSymbolAddress(&p, g_lo);    float* lo    = (float*)p;
    cudaGetSymbolAddress(&p, g_lnlo);  float* lnlo  = (float*)p;
    cudaGetSymbolAddress(&p, g_h1);    float* h1    = (float*)p;
    cudaGetSymbolAddress(&p, g_lo2);   float* lo2   = (float*)p;
    cudaGetSymbolAddress(&p, g_wq);    float* wq    = (float*)p;
    cudaGetSymbolAddress(&p, g_wo);    float* wo    = (float*)p;
    cudaGetSymbolAddress(&p, g_w1);    float* w1    = (float*)p;
    cudaGetSymbolAddress(&p, g_w2);    float* w2    = (float*)p;
    float* part1 = part + (size_t)16 * 256 * 256;

    // fork
    cudaEventRecord(e0, 0);
    cudaStreamWaitEvent(s1, e0, 0);
    cudaStreamWaitEvent(s2, e0, 0);
    cudaStreamWaitEvent(s3, e0, 0);

    // s3: weight pre-rounding, then mask uploads
    cvt_tf32_k<<<(768 * 256 / 4 + 255) / 256, 256, 0, s3>>>(in_w, wq, 768 * 256 / 4);
    cvt_tf32_k<<<(256 * 256 / 4 + 255) / 256, 256, 0, s3>>>(out_w, wo, 256 * 256 / 4);
    cvt_tf32_k<<<(1024 * 256 / 4 + 255) / 256, 256, 0, s3>>>(mlp_w1, w1, 1024 * 256 / 4);
    cvt_tf32_k<<<(256 * 1024 / 4 + 255) / 256, 256, 0, s3>>>(mlp_w2, w2, 256 * 1024 / 4);
    cudaEventRecord(e5, s3);
    cudaMemcpyToSymbolAsync(g_bandmask, h_bandmask, sizeof(h_bandmask), 0, cudaMemcpyHostToDevice, s3);
    cudaMemcpyToSymbolAsync(g_rand16, h_rand16, sizeof(h_rand16), 0, cudaMemcpyHostToDevice, s3);
    cudaMemcpyToSymbolAsync(g_cnt,  h_cnt,  sizeof(h_cnt),  0, cudaMemcpyHostToDevice, s3);
    cudaEventRecord(e3, s3);

    // main: local tokens
    ln_local_k<<<128, 256, 0, 0>>>(x, local_pos, ln_l_g, ln_l_b);

    // s1: adjacency branch 0
    tsplitk_k<1><<<dim3(4, 4, 16), 256, 0, s1>>>(x, adj0_w, part, 256, 256, 4096, 256);
    reduce_ln_k<<<256, 256, 0, s1>>>(part, 256 * 256, 16, adj0_b, reg_pos0,
                                     ln_r0_g, ln_r0_b, feats + (size_t)4096 * 256, 1);
    cudaEventRecord(e1, s1);

    // s2: adjacency branch 1
    tsplitk_k<2><<<dim3(4, 1, 32), 256, 0, s2>>>(x, adj1_w, part1, 64, 256, 16384, 512);
    reduce_ln_k<<<64, 256, 0, s2>>>(part1, 64 * 256, 32, adj1_b, reg_pos1,
                                    ln_r1_g, ln_r1_b, feats + (size_t)4352 * 256, 4);
    cudaEventRecord(e2, s2);

    // join adjacency + weight cvts before qkv
    cudaStreamWaitEvent(0, e1, 0);
    cudaStreamWaitEvent(0, e2, 0);
    cudaStreamWaitEvent(0, e5, 0);
    tgemm_k<128, 1, true><<<dim3(6, 36), 256, 0, 0>>>(feats, wq, in_b, nullptr, qkv, S_TOK, 768, 256);
    cudaEventRecord(eq, 0);

    // s1: independent rand pass (bf16 K/V), concurrent with band attention
    cudaStreamWaitEvent(s1, eq, 0);
    cudaStreamWaitEvent(s1, e3, 0);
    conv_kv_k<<<S_TOK, 256, 0, s1>>>(qkv);
    attn_rand_ind_k<<<4096, 256, 0, s1>>>(qkv);
    cudaEventRecord(e4, s1);

    // main: band attention
    cudaStreamWaitEvent(0, e3, 0);
    attn_band_k<<<dim3(64, 8), 256, 0, 0>>>(qkv, ctx);

    // merge the two softmax partials
    cudaStreamWaitEvent(0, e4, 0);
    merge_attn_k<<<4096, 256, 0, 0>>>(ctx);

    tgemm_k<64, 1, false><<<dim3(4, 32), 256, 0, 0>>>(ctx, wo, out_b, nullptr, lo, HW_TOK, 256, 256);
    ln_rows_k<<<4096, 256, 0, 0>>>(lo, ln_o_g, ln_o_b, lnlo);
    tgemm_k<128, 2, true><<<dim3(8, 32), 256, 0, 0>>>(lnlo, w1, mlp_b1, nullptr, h1, HW_TOK, 1024, 256);
    tgemm_k<64, 3, false><<<dim3(4, 32), 256, 0, 0>>>(h1, w2, mlp_b2, lo, lo2, HW_TOK, 256, 1024);

    finalize_k<<<dim3(128, 8), 256, 0, 0>>>(x, out);
}

// round 17
// speedup vs baseline: 1.3703x; 1.3703x over previous
#include <cuda_runtime.h>
#include <cstdint>
#include <cstring>
#include <cmath>
#include <algorithm>
#include <thread>
#include <vector>

#define TF_PARTITIONABLE 1

#define S_TOK   4608
#define HW_TOK  4096
#define NCH     256
#define HALF_BAND 230
#define NRAND   115
#define RAND_PITCH 116
#define BWIN_W  18

// ---------------- device scratch ----------------
__device__ float    g_feats[S_TOK * NCH];
__device__ float    g_part[32 * 256 * 256];
__device__ float    g_qkv[S_TOK * 768];
__device__ float    g_ctx[HW_TOK * NCH];
__device__ float    g_lo[HW_TOK * NCH];
__device__ float    g_lnlo[HW_TOK * NCH];
__device__ float    g_h1[HW_TOK * 1024];
__device__ uint32_t g_bandmask[HW_TOK * BWIN_W];
__device__ float    g_m[HW_TOK * 8];
__device__ float    g_l[HW_TOK * 8];
__device__ unsigned short g_rand16[HW_TOK * RAND_PITCH];
__device__ int      g_cnt[HW_TOK];
// pre-rounded tf32 weight copies
__device__ float    g_wq[768 * 256];
__device__ float    g_wo[256 * 256];
__device__ float    g_w1[1024 * 256];
__device__ float    g_w2[256 * 1024];

// ---------------- tf32 helpers ----------------
__device__ __forceinline__ uint32_t f2tf(float f)
{ uint32_t u; asm("cvt.rna.tf32.f32 %0, %1;" : "=r"(u) : "f"(f)); return u; }

__device__ __forceinline__ float f2tff(float f)
{ return __uint_as_float(f2tf(f)); }

__device__ __forceinline__ void mma_tf32(float* c, const uint32_t* a, const uint32_t* b)
{
    asm volatile(
        "mma.sync.aligned.m16n8k8.row.col.f32.tf32.tf32.f32 "
        "{%0,%1,%2,%3},{%4,%5,%6,%7},{%8,%9},{%0,%1,%2,%3};"
        : "+f"(c[0]), "+f"(c[1]), "+f"(c[2]), "+f"(c[3])
        : "r"(a[0]), "r"(a[1]), "r"(a[2]), "r"(a[3]), "r"(b[0]), "r"(b[1]));
}

__device__ __forceinline__ float gelu_f(float v)
{ return 0.5f * v * (1.0f + erff(v * 0.70710678118654752f)); }

// ---------------- weight pre-rounding ----------------
__global__ __launch_bounds__(256) void cvt_tf32_k(const float* __restrict__ src,
                                                  float* __restrict__ dst, int n4)
{
    int i = blockIdx.x * 256 + threadIdx.x;
    if (i < n4) {
        float4 v = ((const float4*)src)[i];
        v.x = f2tff(v.x); v.y = f2tff(v.y); v.z = f2tff(v.z); v.w = f2tff(v.w);
        ((float4*)dst)[i] = v;
    }
}

// ---------------- LN of local tokens (emits tf32-rounded feats) ----------------
__global__ __launch_bounds__(256) void ln_local_k(
    const float* __restrict__ x, const float* __restrict__ pos,
    const float* __restrict__ g, const float* __restrict__ b)
{
    __shared__ float tile[256][33];
    const int t0 = blockIdx.x * 32;
    const int lane = threadIdx.x & 31, wid = threadIdx.x >> 5;
    #pragma unroll 8
    for (int it = 0; it < 32; it++) {
        int c = it * 8 + wid;
        tile[c][lane] = x[(size_t)c * HW_TOK + t0 + lane];
    }
    __syncthreads();
    for (int tt = 0; tt < 4; tt++) {
        int tok = wid * 4 + tt;
        float v[8], s = 0.f, sq = 0.f;
        #pragma unroll
        for (int i = 0; i < 8; i++) {
            int c = lane + 32 * i;
            v[i] = tile[c][tok] + pos[c];
            s += v[i]; sq += v[i] * v[i];
        }
        #pragma unroll
        for (int o = 16; o; o >>= 1) {
            s  += __shfl_xor_sync(0xffffffffu, s, o);
            sq += __shfl_xor_sync(0xffffffffu, sq, o);
        }
        float m = s * (1.f / 256.f);
        float var = sq * (1.f / 256.f) - m * m;
        float rs = rsqrtf(var + 1e-5f);
        #pragma unroll
        for (int i = 0; i < 8; i++) {
            int c = lane + 32 * i;
            g_feats[(size_t)(t0 + tok) * NCH + c] = f2tff((v[i] - m) * rs * g[c] + b[c]);
        }
    }
}

// ---------------- row LN (emits tf32-rounded) ----------------
__global__ __launch_bounds__(256) void ln_rows_k(
    const float* __restrict__ in,
    const float* __restrict__ g, const float* __restrict__ b,
    float* __restrict__ out)
{
    int row = blockIdx.x, c = threadIdx.x;
    float v = in[(size_t)row * 256 + c];
    float s = v, sq = v * v;
    #pragma unroll
    for (int o = 16; o; o >>= 1) {
        s  += __shfl_xor_sync(0xffffffffu, s, o);
        sq += __shfl_xor_sync(0xffffffffu, sq, o);
    }
    __shared__ float ss[8], qq[8];
    int wid = c >> 5, lane = c & 31;
    if (!lane) { ss[wid] = s; qq[wid] = sq; }
    __syncthreads();
    float ts = 0.f, tq = 0.f;
    #pragma unroll
    for (int i = 0; i < 8; i++) { ts += ss[i]; tq += qq[i]; }
    float m = ts * (1.f / 256.f);
    float var = tq * (1.f / 256.f) - m * m;
    float rs = rsqrtf(var + 1e-5f);
    out[(size_t)row * 256 + c] = f2tff((v - m) * rs * g[c] + b[c]);
}

// ---------------- fused split-K reduce + add + LN + replicate ----------------
__global__ __launch_bounds__(256) void reduce_ln_k(
    const float* __restrict__ part, int stride, int Z,
    const float* __restrict__ add1, const float* __restrict__ add2,
    const float* __restrict__ g, const float* __restrict__ b,
    float* __restrict__ out, int rep)
{
    int row = blockIdx.x, c = threadIdx.x;
    float v = 0.f;
    for (int z = 0; z < Z; z++) v += part[(size_t)z * stride + row * 256 + c];
    v += add1[c] + add2[c];
    float s = v, sq = v * v;
    #pragma unroll
    for (int o = 16; o; o >>= 1) {
        s  += __shfl_xor_sync(0xffffffffu, s, o);
        sq += __shfl_xor_sync(0xffffffffu, sq, o);
    }
    __shared__ float ss[8], qq[8];
    int wid = c >> 5, lane = c & 31;
    if (!lane) { ss[wid] = s; qq[wid] = sq; }
    __syncthreads();
    float ts = 0.f, tq = 0.f;
    #pragma unroll
    for (int i = 0; i < 8; i++) { ts += ss[i]; tq += qq[i]; }
    float m = ts * (1.f / 256.f);
    float var = tq * (1.f / 256.f) - m * m;
    float rs = rsqrtf(var + 1e-5f);
    float o = f2tff((v - m) * rs * g[c] + b[c]);
    for (int k = 0; k < rep; k++)
        out[(size_t)(row * rep + k) * 256 + c] = o;
}

// ---------------- gather-fused A load for adjacency ----------------
template <int G>
__device__ __forceinline__ float4 loadA_g(const float* __restrict__ A, int row, int col, int K)
{
    if (G == 1) {
        int c = col >> 4, i = (col >> 2) & 3;
        int bh = row >> 4, bw = row & 15;
        return *(const float4*)(A + (size_t)c * HW_TOK + (bh * 4 + i) * 64 + bw * 4);
    }
    int c = col >> 6, i = (col >> 3) & 7, j = col & 7;
    int bh = row >> 3, bw = row & 7;
    return *(const float4*)(A + (size_t)c * HW_TOK + (bh * 8 + i) * 64 + bw * 8 + j);
}

// ---------------- tf32 split-K 64x64x32 GEMM with gather-fused A ----------------
template <int G>
__global__ __launch_bounds__(256) void tsplitk_k(
    const float* __restrict__ A, const float* __restrict__ B,
    float* __restrict__ Cpart, int M, int N, int K, int kPerZ)
{
    constexpr int SA = 36;
    __shared__ uint32_t As[64 * SA];
    __shared__ uint32_t Bs[64 * SA];
    const int tid = threadIdx.x;
    const int lane = tid & 31, wid = tid >> 5;
    const int bm = blockIdx.y * 64, bn = blockIdx.x * 64;
    const int m0 = (wid & 3) * 16, n0 = (wid >> 2) * 32;
    const int r = lane >> 2, qc = lane & 3;
    const int row = tid >> 2, col8 = (tid & 3) * 8;
    const int k0 = blockIdx.z * kPerZ;

    float acc[4][4] = {};
    for (int kt = 0; kt < kPerZ; kt += 32) {
        float4 a0 = loadA_g<G>(A, bm + row, k0 + kt + col8, K);
        float4 a1 = loadA_g<G>(A, bm + row, k0 + kt + col8 + 4, K);
        float4 b0 = *(const float4*)(B + (size_t)(bn + row) * K + k0 + kt + col8);
        float4 b1 = *(const float4*)(B + (size_t)(bn + row) * K + k0 + kt + col8 + 4);
        __syncthreads();
        uint32_t* da = &As[row * SA + col8];
        da[0] = f2tf(a0.x); da[1] = f2tf(a0.y); da[2] = f2tf(a0.z); da[3] = f2tf(a0.w);
        da[4] = f2tf(a1.x); da[5] = f2tf(a1.y); da[6] = f2tf(a1.z); da[7] = f2tf(a1.w);
        uint32_t* db = &Bs[row * SA + col8];
        db[0] = f2tf(b0.x); db[1] = f2tf(b0.y); db[2] = f2tf(b0.z); db[3] = f2tf(b0.w);
        db[4] = f2tf(b1.x); db[5] = f2tf(b1.y); db[6] = f2tf(b1.z); db[7] = f2tf(b1.w);
        __syncthreads();
        #pragma unroll
        for (int ks = 0; ks < 4; ks++) {
            int kk = ks * 8;
            uint32_t af[4];
            af[0] = As[(m0 + r) * SA + kk + qc];
            af[1] = As[(m0 + r + 8) * SA + kk + qc];
            af[2] = As[(m0 + r) * SA + kk + qc + 4];
            af[3] = As[(m0 + r + 8) * SA + kk + qc + 4];
            #pragma unroll
            for (int ni = 0; ni < 4; ni++) {
                uint32_t bf[2];
                bf[0] = Bs[(n0 + ni * 8 + r) * SA + kk + qc];
                bf[1] = Bs[(n0 + ni * 8 + r) * SA + kk + qc + 4];
                mma_tf32(acc[ni], af, bf);
            }
        }
    }
    float* Cz = Cpart + (size_t)blockIdx.z * M * N;
    #pragma unroll
    for (int ni = 0; ni < 4; ni++) {
        int c = bn + n0 + ni * 8 + qc * 2;
        Cz[(size_t)(bm + m0 + r) * N + c]         = acc[ni][0];
        Cz[(size_t)(bm + m0 + r) * N + c + 1]     = acc[ni][1];
        Cz[(size_t)(bm + m0 + r + 8) * N + c]     = acc[ni][2];
        Cz[(size_t)(bm + m0 + r + 8) * N + c + 1] = acc[ni][3];
    }
}

// ---------------- tf32 tensor-core GEMM (A and B pre-rounded: no CVT) ----------------
// EPI: 1=+bias, 2=+bias+gelu, 4=+bias+res(lo)+resT(x), transposed store to C[col*HW+row]
template <int BN, int EPI, bool RND>
__global__ __launch_bounds__(256) void tgemm_k(
    const float* __restrict__ A, const float* __restrict__ B,
    const float* __restrict__ bias, const float* __restrict__ res,
    const float* __restrict__ resT,
    float* __restrict__ C, int M, int N, int K)
{
    constexpr int SA = 20;
    constexpr int NF = BN / 16;
    __shared__ uint32_t As[2][128 * SA];
    __shared__ uint32_t Bs[2][BN * SA];

    const int tid = threadIdx.x;
    const int lane = tid & 31, wid = tid >> 5;
    const int bm = blockIdx.y * 128, bn = blockIdx.x * BN;
    const int m0 = (wid & 3) * 32;
    const int n0 = (wid >> 2) * (BN / 2);
    const int r = lane >> 2, qc = lane & 3;

    float acc[2][NF][4] = {};

    const int ar = tid >> 1, ac = (tid & 1) * 8;
    const int br = (BN == 128) ? (tid >> 1) : (tid >> 2);
    const int bc = (BN == 128) ? ((tid & 1) * 8) : ((tid & 3) * 4);

    const float* Apt = A + (size_t)(bm + ar) * K + ac;
    const float* Bpt = B + (size_t)(bn + br) * K + bc;

    float4 pa0 = *(const float4*)(Apt);
    float4 pa1 = *(const float4*)(Apt + 4);
    float4 pb0 = *(const float4*)(Bpt);
    float4 pb1;
    if constexpr (BN == 128) pb1 = *(const float4*)(Bpt + 4);

    auto store_stage = [&](int s) {
        *(float4*)&As[s][ar * SA + ac]     = pa0;
        *(float4*)&As[s][ar * SA + ac + 4] = pa1;
        *(float4*)&Bs[s][br * SA + bc]     = pb0;
        if constexpr (BN == 128)
            *(float4*)&Bs[s][br * SA + bc + 4] = pb1;
    };
    auto compute = [&](int s) {
        #pragma unroll
        for (int ks = 0; ks < 2; ks++) {
            int k0 = ks * 8;
            uint32_t af[2][4];
            #pragma unroll
            for (int mi = 0; mi < 2; mi++) {
                int mb = m0 + mi * 16;
                af[mi][0] = As[s][(mb + r) * SA + k0 + qc];
                af[mi][1] = As[s][(mb + r + 8) * SA + k0 + qc];
                af[mi][2] = As[s][(mb + r) * SA + k0 + qc + 4];
                af[mi][3] = As[s][(mb + r + 8) * SA + k0 + qc + 4];
            }
            #pragma unroll
            for (int ni = 0; ni < NF; ni++) {
                uint32_t bf[2];
                bf[0] = Bs[s][(n0 + ni * 8 + r) * SA + k0 + qc];
                bf[1] = Bs[s][(n0 + ni * 8 + r) * SA + k0 + qc + 4];
                mma_tf32(acc[0][ni], af[0], bf);
                mma_tf32(acc[1][ni], af[1], bf);
            }
        }
    };

    store_stage(0);
    __syncthreads();
    int cur = 0;
    const int nst = K / 16;
    for (int st = 1; st < nst; st++) {
        pa0 = *(const float4*)(Apt + st * 16);
        pa1 = *(const float4*)(Apt + st * 16 + 4);
        pb0 = *(const float4*)(Bpt + st * 16);
        if constexpr (BN == 128) pb1 = *(const float4*)(Bpt + st * 16 + 4);
        compute(cur);
        store_stage(cur ^ 1);
        __syncthreads();
        cur ^= 1;
    }
    compute(cur);

    #pragma unroll
    for (int mi = 0; mi < 2; mi++) {
        int rw = bm + m0 + mi * 16 + r;
        int rw2 = rw + 8;
        #pragma unroll
        for (int ni = 0; ni < NF; ni++) {
            int col = bn + n0 + ni * 8 + qc * 2;
            float v0 = acc[mi][ni][0] + bias[col];
            float v1 = acc[mi][ni][1] + bias[col + 1];
            float v2 = acc[mi][ni][2] + bias[col];
            float v3 = acc[mi][ni][3] + bias[col + 1];
            if (EPI == 2) { v0 = gelu_f(v0); v1 = gelu_f(v1); v2 = gelu_f(v2); v3 = gelu_f(v3); }
            if (EPI == 4) {
                v0 += res[(size_t)rw * N + col]      + resT[(size_t)col * HW_TOK + rw];
                v1 += res[(size_t)rw * N + col + 1]  + resT[(size_t)(col + 1) * HW_TOK + rw];
                v2 += res[(size_t)rw2 * N + col]     + resT[(size_t)col * HW_TOK + rw2];
                v3 += res[(size_t)rw2 * N + col + 1] + resT[(size_t)(col + 1) * HW_TOK + rw2];
            }
            if (RND) { v0 = f2tff(v0); v1 = f2tff(v1); v2 = f2tff(v2); v3 = f2tff(v3); }
            if (EPI == 4) {
                C[(size_t)col * HW_TOK + rw]        = v0;
                C[(size_t)(col + 1) * HW_TOK + rw]  = v1;
                C[(size_t)col * HW_TOK + rw2]       = v2;
                C[(size_t)(col + 1) * HW_TOK + rw2] = v3;
            } else {
                C[(size_t)rw * N + col] = v0;  C[(size_t)rw * N + col + 1] = v1;
                C[(size_t)rw2 * N + col] = v2; C[(size_t)rw2 * N + col + 1] = v3;
            }
        }
    }
}

// ---------------- band flash attention, tf32 mma ----------------
__global__ __launch_bounds__(256) void attn_band_k(const float* __restrict__ qkv,
                                                   float* __restrict__ ctx)
{
    __shared__ uint32_t Qs[64 * 36];
    __shared__ uint32_t Ks[64 * 36];
    __shared__ uint32_t Vt[32 * 68];
    __shared__ float    Ss[64 * 68];
    __shared__ uint32_t mw[64][2];
    __shared__ float    s_m[64], s_l[64], s_al[64];

    const int tid = threadIdx.x;
    const int lane = tid & 31, wid = tid >> 5;
    const int h = blockIdx.y, t0 = blockIdx.x * 64;
    const int r = lane >> 2, qc = lane & 3;
    const float scale = 0.17677669529663687f;
    uint32_t* PsU = (uint32_t*)Ss;

    {
        int tok = tid >> 2, d0 = (tid & 3) * 8;
        float4 q0 = *(const float4*)&qkv[(size_t)(t0 + tok) * 768 + h * 32 + d0];
        float4 q1 = *(const float4*)&qkv[(size_t)(t0 + tok) * 768 + h * 32 + d0 + 4];
        uint32_t* dq = &Qs[tok * 36 + d0];
        dq[0] = __float_as_uint(q0.x); dq[1] = __float_as_uint(q0.y);
        dq[2] = __float_as_uint(q0.z); dq[3] = __float_as_uint(q0.w);
        dq[4] = __float_as_uint(q1.x); dq[5] = __float_as_uint(q1.y);
        dq[6] = __float_as_uint(q1.z); dq[7] = __float_as_uint(q1.w);
    }
    if (tid < 64) { s_m[tid] = -INFINITY; s_l[tid] = 0.f; }

    float o_[4][4] = {};

    int lo_t = (t0 >= HALF_BAND) ? ((t0 - HALF_BAND) >> 6) : 0;
    int hi_t = (t0 + 63 + HALF_BAND) >> 6; if (hi_t > 71) hi_t = 71;

    for (int kt = lo_t; kt <= hi_t; kt++) {
        __syncthreads();
        int kb = kt * 64;
        {
            int tok = tid >> 2, d0 = (tid & 3) * 8;
            float4 k0v = *(const float4*)&qkv[(size_t)(kb + tok) * 768 + 256 + h * 32 + d0];
            float4 k1v = *(const float4*)&qkv[(size_t)(kb + tok) * 768 + 256 + h * 32 + d0 + 4];
            uint32_t* dk = &Ks[tok * 36 + d0];
            dk[0] = __float_as_uint(k0v.x); dk[1] = __float_as_uint(k0v.y);
            dk[2] = __float_as_uint(k0v.z); dk[3] = __float_as_uint(k0v.w);
            dk[4] = __float_as_uint(k1v.x); dk[5] = __float_as_uint(k1v.y);
            dk[6] = __float_as_uint(k1v.z); dk[7] = __float_as_uint(k1v.w);
            float4 v0v = *(const float4*)&qkv[(size_t)(kb + tok) * 768 + 512 + h * 32 + d0];
            float4 v1v = *(const float4*)&qkv[(size_t)(kb + tok) * 768 + 512 + h * 32 + d0 + 4];
            Vt[(d0 + 0) * 68 + tok] = __float_as_uint(v0v.x);
            Vt[(d0 + 1) * 68 + tok] = __float_as_uint(v0v.y);
            Vt[(d0 + 2) * 68 + tok] = __float_as_uint(v0v.z);
            Vt[(d0 + 3) * 68 + tok] = __float_as_uint(v0v.w);
            Vt[(d0 + 4) * 68 + tok] = __float_as_uint(v1v.x);
            Vt[(d0 + 5) * 68 + tok] = __float_as_uint(v1v.y);
            Vt[(d0 + 6) * 68 + tok] = __float_as_uint(v1v.z);
            Vt[(d0 + 7) * 68 + tok] = __float_as_uint(v1v.w);
        }
        if (tid < 128)
            mw[tid >> 1][tid & 1] =
                g_bandmask[(size_t)(t0 + (tid >> 1)) * BWIN_W + (kt - lo_t) * 2 + (tid & 1)];
        __syncthreads();

        {
            const int m0 = (wid & 3) * 16, nh = (wid >> 2) * 32;
            float sf[4][4] = {};
            #pragma unroll
            for (int ks = 0; ks < 4; ks++) {
                int k0 = ks * 8;
                uint32_t af[4];
                af[0] = Qs[(m0 + r) * 36 + k0 + qc];
                af[1] = Qs[(m0 + r + 8) * 36 + k0 + qc];
                af[2] = Qs[(m0 + r) * 36 + k0 + qc + 4];
                af[3] = Qs[(m0 + r + 8) * 36 + k0 + qc + 4];
                #pragma unroll
                for (int ni = 0; ni < 4; ni++) {
                    uint32_t bf[2];
                    bf[0] = Ks[(nh + ni * 8 + r) * 36 + k0 + qc];
                    bf[1] = Ks[(nh + ni * 8 + r) * 36 + k0 + qc + 4];
                    mma_tf32(sf[ni], af, bf);
                }
            }
            #pragma unroll
            for (int ni = 0; ni < 4; ni++) {
                int c0 = nh + ni * 8 + qc * 2;
                int rowA = m0 + r, rowB = m0 + r + 8;
                uint32_t wA0 = (mw[rowA][c0 >> 5] >> (c0 & 31)) & 1u;
                uint32_t wA1 = (mw[rowA][(c0 + 1) >> 5] >> ((c0 + 1) & 31)) & 1u;
                uint32_t wB0 = (mw[rowB][c0 >> 5] >> (c0 & 31)) & 1u;
                uint32_t wB1 = (mw[rowB][(c0 + 1) >> 5] >> ((c0 + 1) & 31)) & 1u;
                Ss[rowA * 68 + c0]     = wA0 ? sf[ni][0] * scale : -INFINITY;
                Ss[rowA * 68 + c0 + 1] = wA1 ? sf[ni][1] * scale : -INFINITY;
                Ss[rowB * 68 + c0]     = wB0 ? sf[ni][2] * scale : -INFINITY;
                Ss[rowB * 68 + c0 + 1] = wB1 ? sf[ni][3] * scale : -INFINITY;
            }
        }
        __syncthreads();

        {
            int row = tid >> 2, c0 = (tid & 3) * 16;
            float sv[16], mx = -INFINITY;
            #pragma unroll
            for (int j = 0; j < 16; j++) {
                sv[j] = Ss[row * 68 + c0 + j];
                mx = fmaxf(mx, sv[j]);
            }
            mx = fmaxf(mx, __shfl_xor_sync(0xffffffffu, mx, 1));
            mx = fmaxf(mx, __shfl_xor_sync(0xffffffffu, mx, 2));
            float m_old = s_m[row];
            float m_new = fmaxf(m_old, mx);
            float al, ps = 0.f;
            if (m_new == -INFINITY) {
                al = 1.f;
                #pragma unroll
                for (int j = 0; j < 16; j++)
                    PsU[row * 68 + c0 + j] = 0u;
            } else {
                al = __expf(m_old - m_new);
                #pragma unroll
                for (int j = 0; j < 16; j++) {
                    float pv = __expf(sv[j] - m_new);
                    ps += pv;
                    PsU[row * 68 + c0 + j] = f2tf(pv);
                }
            }
            ps += __shfl_xor_sync(0xffffffffu, ps, 1);
            ps += __shfl_xor_sync(0xffffffffu, ps, 2);
            if ((tid & 3) == 0) {
                s_l[row] = s_l[row] * al + ps;
                s_m[row] = m_new;
                s_al[row] = al;
            }
        }
        __syncthreads();

        if (wid < 4) {
            const int m0 = wid * 16;
            float alA = s_al[m0 + r], alB = s_al[m0 + r + 8];
            #pragma unroll
            for (int ni = 0; ni < 4; ni++) {
                o_[ni][0] *= alA; o_[ni][1] *= alA;
                o_[ni][2] *= alB; o_[ni][3] *= alB;
            }
            #pragma unroll
            for (int ks = 0; ks < 8; ks++) {
                int k0 = ks * 8;
                uint32_t af[4];
                af[0] = PsU[(m0 + r) * 68 + k0 + qc];
                af[1] = PsU[(m0 + r + 8) * 68 + k0 + qc];
                af[2] = PsU[(m0 + r) * 68 + k0 + qc + 4];
                af[3] = PsU[(m0 + r + 8) * 68 + k0 + qc + 4];
                #pragma unroll
                for (int ni = 0; ni < 4; ni++) {
                    uint32_t bf[2];
                    bf[0] = Vt[(ni * 8 + r) * 68 + k0 + qc];
                    bf[1] = Vt[(ni * 8 + r) * 68 + k0 + qc + 4];
                    mma_tf32(o_[ni], af, bf);
                }
            }
        }
    }
    __syncthreads();

    if (wid < 4) {
        const int m0 = wid * 16;
        int rowA = t0 + m0 + r, rowB = rowA + 8;
        #pragma unroll
        for (int ni = 0; ni < 4; ni++) {
            int col = h * 32 + ni * 8 + qc * 2;
            ctx[(size_t)rowA * 256 + col]     = o_[ni][0];
            ctx[(size_t)rowA * 256 + col + 1] = o_[ni][1];
            ctx[(size_t)rowB * 256 + col]     = o_[ni][2];
            ctx[(size_t)rowB * 256 + col + 1] = o_[ni][3];
        }
    }
    if (tid < 64) {
        g_m[(t0 + tid) * 8 + h] = s_m[tid];
        g_l[(t0 + tid) * 8 + h] = s_l[tid];
    }
}

// ---------------- random-key pass: low-latency score phase ----------------
// Phase 1: warp w handles keys w, w+8, ... For each key the warp computes ALL
// 8 head scores at once: lane l covers channels [8l, 8l+8); head h = lanes
// [4h,4h+4) -> 2-shfl segmented reduction.
__global__ __launch_bounds__(256) void attn_rand_k(const float* __restrict__ qkv,
                                                   float* __restrict__ ctx)
{
    __shared__ float sS[8][120];
    __shared__ int   sK[NRAND + 1];
    const int row = blockIdx.x;
    const int tid = threadIdx.x;
    const int w = tid >> 5;
    const int lane = tid & 31;
    const int ch = w * 32 + lane;
    const float scale = 0.17677669529663687f;

    const int cnt = g_cnt[row];
    if (tid < cnt)
        sK[tid] = g_rand16[(size_t)row * RAND_PITCH + tid];
    __syncthreads();

    // phase 1: scores, all heads per key
    {
        const float* qp = qkv + (size_t)row * 768 + lane * 8;
        float4 q0 = *(const float4*)qp;
        float4 q1 = *(const float4*)(qp + 4);
        for (int i = w; i < cnt; i += 8) {
            const float* kp = qkv + (size_t)sK[i] * 768 + 256 + lane * 8;
            float4 k0 = *(const float4*)kp;
            float4 k1 = *(const float4*)(kp + 4);
            float s = q0.x * k0.x + q0.y * k0.y + q0.z * k0.z + q0.w * k0.w
                    + q1.x * k1.x + q1.y * k1.y + q1.z * k1.z + q1.w * k1.w;
            s += __shfl_xor_sync(0xffffffffu, s, 1);
            s += __shfl_xor_sync(0xffffffffu, s, 2);
            if ((lane & 3) == 0) sS[lane >> 2][i] = s * scale;
        }
    }
    __syncthreads();

    // phase 2: merge stats with band partials (warp w = head w)
    float m_b = g_m[row * 8 + w];
    float l_b = g_l[row * 8 + w];
    float mx = -INFINITY;
    for (int i = lane; i < cnt; i += 32) mx = fmaxf(mx, sS[w][i]);
    #pragma unroll
    for (int off = 16; off; off >>= 1)
        mx = fmaxf(mx, __shfl_xor_sync(0xffffffffu, mx, off));
    float m_new = fmaxf(m_b, mx);
    float psum = 0.f;
    for (int i = lane; i < cnt; i += 32) {
        float p = __expf(sS[w][i] - m_new);
        sS[w][i] = p;
        psum += p;
    }
    #pragma unroll
    for (int off = 16; off; off >>= 1)
        psum += __shfl_xor_sync(0xffffffffu, psum, off);
    __syncwarp();

    float al = __expf(m_b - m_new);
    float l = l_b * al + psum;
    float o = ctx[(size_t)row * 256 + ch] * al;

    // phase 3: PV (independent loads)
    for (int i = 0; i < cnt; i++)
        o += sS[w][i] * qkv[(size_t)sK[i] * 768 + 512 + ch];

    ctx[(size_t)row * 256 + ch] = f2tff(o / l);
}

// ================= host: threefry2x32 + jax mask replication =================
static inline uint32_t rotl32(uint32_t x, int r) { return (x << r) | (x >> (32 - r)); }

static void tf2x32(uint32_t k0, uint32_t k1, uint32_t x0, uint32_t x1,
                   uint32_t& o0, uint32_t& o1)
{
    uint32_t ks0 = k0, ks1 = k1, ks2 = k0 ^ k1 ^ 0x1BD11BDAu;
    static const int ra[4] = {13, 15, 26, 6}, rb[4] = {17, 29, 16, 24};
    x0 += ks0; x1 += ks1;
    for (int i = 0; i < 4; i++) { x0 += x1; x1 = rotl32(x1, ra[i]); x1 ^= x0; }
    x0 += ks1; x1 += ks2 + 1;
    for (int i = 0; i < 4; i++) { x0 += x1; x1 = rotl32(x1, rb[i]); x1 ^= x0; }
    x0 += ks2; x1 += ks0 + 2;
    for (int i = 0; i < 4; i++) { x0 += x1; x1 = rotl32(x1, ra[i]); x1 ^= x0; }
    x0 += ks0; x1 += ks1 + 3;
    for (int i = 0; i < 4; i++) { x0 += x1; x1 = rotl32(x1, rb[i]); x1 ^= x0; }
    x0 += ks1; x1 += ks2 + 4;
    for (int i = 0; i < 4; i++) { x0 += x1; x1 = rotl32(x1, ra[i]); x1 ^= x0; }
    x0 += ks2; x1 += ks0 + 5;
    o0 = x0; o1 = x1;
}

static void split2(uint32_t k0, uint32_t k1,
                   uint32_t& a0, uint32_t& a1, uint32_t& s0, uint32_t& s1)
{
#if TF_PARTITIONABLE
    tf2x32(k0, k1, 0u, 0u, a0, a1);
    tf2x32(k0, k1, 0u, 1u, s0, s1);
#else
    uint32_t w0, w2, w1, w3;
    tf2x32(k0, k1, 0u, 2u, w0, w2);
    tf2x32(k0, k1, 1u, 3u, w1, w3);
    a0 = w0; a1 = w1; s0 = w2; s1 = w3;
#endif
}

static void bits_n(uint32_t k0, uint32_t k1, uint32_t* out)
{
#if TF_PARTITIONABLE
    for (uint32_t i = 0; i < S_TOK; i++) {
        uint32_t o0, o1;
        tf2x32(k0, k1, 0u, i, o0, o1);
        out[i] = o0 ^ o1;
    }
#else
    const uint32_t half = S_TOK / 2;
    for (uint32_t i = 0; i < half; i++) {
        uint32_t o0, o1;
        tf2x32(k0, k1, i, i + half, o0, o1);
        out[i] = o0; out[i + half] = o1;
    }
#endif
}

static void row_key(int r, uint32_t& k0, uint32_t& k1)
{
#if TF_PARTITIONABLE
    tf2x32(0u, 42u, 0u, (uint32_t)r, k0, k1);
#else
    uint32_t j0 = 2u * r, j1 = 2u * r + 1;
    uint32_t o0, o1;
    if (j0 < S_TOK) { tf2x32(0u, 42u, j0, j0 + S_TOK, o0, o1); k0 = o0; }
    else            { tf2x32(0u, 42u, j0 - S_TOK, j0, o0, o1); k0 = o1; }
    if (j1 < S_TOK) { tf2x32(0u, 42u, j1, j1 + S_TOK, o0, o1); k1 = o0; }
    else            { tf2x32(0u, 42u, j1 - S_TOK, j1, o0, o1); k1 = o1; }
#endif
}

static uint32_t       h_bandmask[HW_TOK * BWIN_W];
static unsigned short h_rand16[HW_TOK * RAND_PITCH];
static int            h_cnt[HW_TOK];

static void build_rows(int r0, int r1)
{
    std::vector<uint64_t> buf(S_TOK);
    std::vector<uint32_t> bits(S_TOK);
    std::vector<int> perm(S_TOK);
    for (int r = r0; r < r1; r++) {
        uint32_t k0, k1; row_key(r, k0, k1);
        uint32_t a0, a1, s0, s1;
        split2(k0, k1, a0, a1, s0, s1);
        bits_n(s0, s1, bits.data());
        for (int i = 0; i < S_TOK; i++) buf[i] = ((uint64_t)bits[i] << 32) | (uint32_t)i;
        std::sort(buf.begin(), buf.end());
        for (int i = 0; i < S_TOK; i++) perm[i] = (int)(buf[i] & 0xffffffffu);
        uint32_t b0, b1, t0k, t1k;
        split2(a0, a1, b0, b1, t0k, t1k);
        bits_n(t0k, t1k, bits.data());
        for (int i = 0; i < S_TOK; i++) buf[i] = ((uint64_t)bits[i] << 32) | (uint32_t)i;
        std::sort(buf.begin(), buf.end());

        int t0 = r & ~63;
        int lo_t = (t0 >= HALF_BAND) ? ((t0 - HALF_BAND) >> 6) : 0;
        int hi_t = (t0 + 63 + HALF_BAND) >> 6; if (hi_t > 71) hi_t = 71;
        int base = lo_t * 64, top = hi_t * 64 + 63;

        uint32_t* mrow = h_bandmask + (size_t)r * BWIN_W;
        memset(mrow, 0, BWIN_W * sizeof(uint32_t));
        int lo = r - HALF_BAND; if (lo < 0) lo = 0;
        int hi = r + HALF_BAND; if (hi > S_TOK - 1) hi = S_TOK - 1;
        for (int k = lo; k <= hi; k++) {
            int idx = k - base;
            mrow[idx >> 5] |= 1u << (idx & 31);
        }
        int cnt = 0;
        for (int i = 0; i < NRAND; i++) {
            int k = perm[(int)(buf[i] & 0xffffffffu)];
            if (k >= base && k <= top) {
                int idx = k - base;
                mrow[idx >> 5] |= 1u << (idx & 31);
            } else {
                h_rand16[(size_t)r * RAND_PITCH + cnt++] = (unsigned short)k;
            }
        }
        h_cnt[r] = cnt;
    }
}

// ================= launch =================
extern "C" void kernel_launch(void* const* d_in, const int* in_sizes, int n_in,
                              void* d_out, int out_size)
{
    (void)in_sizes; (void)n_in; (void)out_size;
    const float* x         = (const float*)d_in[0];
    const float* local_pos = (const float*)d_in[1];
    const float* reg_pos0  = (const float*)d_in[2];
    const float* reg_pos1  = (const float*)d_in[3];
    const float* ln_l_g    = (const float*)d_in[4];
    const float* ln_l_b    = (const float*)d_in[5];
    const float* ln_r0_g   = (const float*)d_in[6];
    const float* ln_r0_b   = (const float*)d_in[7];
    const float* ln_r1_g   = (const float*)d_in[8];
    const float* ln_r1_b   = (const float*)d_in[9];
    const float* adj0_w    = (const float*)d_in[10];
    const float* adj0_b    = (const float*)d_in[11];
    const float* adj1_w    = (const float*)d_in[12];
    const float* adj1_b    = (const float*)d_in[13];
    const float* in_w      = (const float*)d_in[14];
    const float* in_b      = (const float*)d_in[15];
    const float* out_w     = (const float*)d_in[16];
    const float* out_b     = (const float*)d_in[17];
    const float* ln_o_g    = (const float*)d_in[18];
    const float* ln_o_b    = (const float*)d_in[19];
    const float* mlp_w1    = (const float*)d_in[20];
    const float* mlp_b1    = (const float*)d_in[21];
    const float* mlp_w2    = (const float*)d_in[22];
    const float* mlp_b2    = (const float*)d_in[23];
    float* out = (float*)d_out;

    {
        unsigned hc = std::thread::hardware_concurrency();
        int nt = (int)(hc ? (hc > 64 ? 64 : hc) : 8);
        std::vector<std::thread> th;
        int per = (HW_TOK + nt - 1) / nt;
        for (int t = 0; t < nt; t++) {
            int r0 = t * per, r1 = r0 + per; if (r1 > HW_TOK) r1 = HW_TOK;
            if (r0 < r1) th.emplace_back(build_rows, r0, r1);
        }
        for (auto& t : th) t.join();
    }

    static cudaStream_t s1 = nullptr, s2 = nullptr, s3 = nullptr;
    static cudaEvent_t e0 = nullptr, e1 = nullptr, e2 = nullptr, e3 = nullptr,
                       e5 = nullptr;
    if (!s1) {
        cudaStreamCreateWithFlags(&s1, cudaStreamNonBlocking);
        cudaStreamCreateWithFlags(&s2, cudaStreamNonBlocking);
        cudaStreamCreateWithFlags(&s3, cudaStreamNonBlocking);
        cudaEventCreateWithFlags(&e0, cudaEventDisableTiming);
        cudaEventCreateWithFlags(&e1, cudaEventDisableTiming);
        cudaEventCreateWithFlags(&e2, cudaEventDisableTiming);
        cudaEventCreateWithFlags(&e3, cudaEventDisableTiming);
        cudaEventCreateWithFlags(&e5, cudaEventDisableTiming);
    }

    void* p;
    cudaGetSymbolAddress(&p, g_feats); float* feats = (float*)p;
    cudaGetSymbolAddress(&p, g_part);  float* part  = (float*)p;
    cudaGetSymbolAddress(&p, g_qkv);   float* qkv   = (float*)p;
    cudaGetSymbolAddress(&p, g_ctx);   float* ctx   = (float*)p;
    cudaGetSymbolAddress(&p, g_lo);    float* lo    = (float*)p;
    cudaGetSymbolAddress(&p, g_lnlo);  float* lnlo  = (float*)p;
    cudaGetSymbolAddress(&p, g_h1);    float* h1    = (float*)p;
    cudaGetSymbolAddress(&p, g_wq);    float* wq    = (float*)p;
    cudaGetSymbolAddress(&p, g_wo);    float* wo    = (float*)p;
    cudaGetSymbolAddress(&p, g_w1);    float* w1    = (float*)p;
    cudaGetSymbolAddress(&p, g_w2);    float* w2    = (float*)p;
    float* part1 = part + (size_t)16 * 256 * 256;

    // fork
    cudaEventRecord(e0, 0);
    cudaStreamWaitEvent(s1, e0, 0);
    cudaStreamWaitEvent(s2, e0, 0);
    cudaStreamWaitEvent(s3, e0, 0);

    // s3: weight pre-rounding, then mask uploads
    cvt_tf32_k<<<(768 * 256 / 4 + 255) / 256, 256, 0, s3>>>(in_w, wq, 768 * 256 / 4);
    cvt_tf32_k<<<(256 * 256 / 4 + 255) / 256, 256, 0, s3>>>(out_w, wo, 256 * 256 / 4);
    cvt_tf32_k<<<(1024 * 256 / 4 + 255) / 256, 256, 0, s3>>>(mlp_w1, w1, 1024 * 256 / 4);
    cvt_tf32_k<<<(256 * 1024 / 4 + 255) / 256, 256, 0, s3>>>(mlp_w2, w2, 256 * 1024 / 4);
    cudaEventRecord(e5, s3);
    cudaMemcpyToSymbolAsync(g_bandmask, h_bandmask, sizeof(h_bandmask), 0, cudaMemcpyHostToDevice, s3);
    cudaMemcpyToSymbolAsync(g_rand16, h_rand16, sizeof(h_rand16), 0, cudaMemcpyHostToDevice, s3);
    cudaMemcpyToSymbolAsync(g_cnt,  h_cnt,  sizeof(h_cnt),  0, cudaMemcpyHostToDevice, s3);
    cudaEventRecord(e3, s3);

    // main: local tokens
    ln_local_k<<<128, 256, 0, 0>>>(x, local_pos, ln_l_g, ln_l_b);

    // s1: adjacency branch 0
    tsplitk_k<1><<<dim3(4, 4, 16), 256, 0, s1>>>(x, adj0_w, part, 256, 256, 4096, 256);
    reduce_ln_k<<<256, 256, 0, s1>>>(part, 256 * 256, 16, adj0_b, reg_pos0,
                                     ln_r0_g, ln_r0_b, feats + (size_t)4096 * 256, 1);
    cudaEventRecord(e1, s1);

    // s2: adjacency branch 1
    tsplitk_k<2><<<dim3(4, 1, 32), 256, 0, s2>>>(x, adj1_w, part1, 64, 256, 16384, 512);
    reduce_ln_k<<<64, 256, 0, s2>>>(part1, 64 * 256, 32, adj1_b, reg_pos1,
                                    ln_r1_g, ln_r1_b, feats + (size_t)4352 * 256, 4);
    cudaEventRecord(e2, s2);

    // join adjacency + weight cvts before qkv
    cudaStreamWaitEvent(0, e1, 0);
    cudaStreamWaitEvent(0, e2, 0);
    cudaStreamWaitEvent(0, e5, 0);
    tgemm_k<128, 1, true><<<dim3(6, 36), 256, 0, 0>>>(feats, wq, in_b, nullptr, nullptr, qkv, S_TOK, 768, 256);

    // join mask uploads before attention
    cudaStreamWaitEvent(0, e3, 0);
    attn_band_k<<<dim3(64, 8), 256, 0, 0>>>(qkv, ctx);
    attn_rand_k<<<4096, 256, 0, 0>>>(qkv, ctx);

    tgemm_k<64, 1, false><<<dim3(4, 32), 256, 0, 0>>>(ctx, wo, out_b, nullptr, nullptr, lo, HW_TOK, 256, 256);
    ln_rows_k<<<4096, 256, 0, 0>>>(lo, ln_o_g, ln_o_b, lnlo);
    tgemm_k<128, 2, true><<<dim3(8, 32), 256, 0, 0>>>(lnlo, w1, mlp_b1, nullptr, nullptr, h1, HW_TOK, 1024, 256);
    // mlp2 fused with +lo residual, +x (transposed) and transposed store to out
    tgemm_k<64, 4, false><<<dim3(4, 32), 256, 0, 0>>>(h1, w2, mlp_b2, lo, x, out, HW_TOK, 256, 1024);
}